// round 3
// baseline (speedup 1.0000x reference)
#include <cuda_runtime.h>
#include <cuda_fp16.h>
#include <cstdint>

#define IN_F   4096
#define OUT_F  11008
#define TOKENS 8192

// Scratch (static device globals: allowed; no runtime allocation)
__device__ __half g_xh[(size_t)TOKENS * IN_F];          // x in fp16, [M, K]
__device__ __half g_wT[(size_t)OUT_F * IN_F];           // dequant W^T, [N, K]

// ---------------------------------------------------------------- common helpers
__device__ __forceinline__ uint32_t smem_u32(const void* p) {
    uint32_t a;
    asm("{ .reg .u64 t; cvta.to.shared.u64 t, %1; cvt.u32.u64 %0, t; }" : "=r"(a) : "l"(p));
    return a;
}

#define SWZ128(o) ((o) ^ (((o) >> 3) & 0x70))

#define CP_ASYNC16(dst, src) \
    asm volatile("cp.async.cg.shared.global [%0], [%1], 16;\n" :: "r"(dst), "l"(src))
#define CP_COMMIT()   asm volatile("cp.async.commit_group;\n" ::: "memory")
#define CP_WAIT0()    asm volatile("cp.async.wait_group 0;\n" ::: "memory")
#define CP_WAIT1()    asm volatile("cp.async.wait_group 1;\n" ::: "memory")
#define CP_WAIT2()    asm volatile("cp.async.wait_group 2;\n" ::: "memory")

// ---------------------------------------------------------------- tcgen05 helpers (sm_103a pass only)
static constexpr uint64_t SMEM_DESC_BASE_SW128 =
    (uint64_t(2) << 61) | (uint64_t(1) << 46) | (uint64_t(64) << 32) | (uint64_t(1) << 16);
#define MAKE_SMEM_DESC(base_addr) (SMEM_DESC_BASE_SW128 | ((uint64_t)((base_addr) >> 4) & 0x3FFF))

#define MBARRIER_INIT(addr, cnt) \
    asm volatile("mbarrier.init.shared.b64 [%0], %1;" :: "r"((uint32_t)(addr)), "r"((uint32_t)(cnt)) : "memory")

#define MBARRIER_WAIT_PARITY(mbar_smem_addr, phase_parity) do {                              \
    uint32_t _mbar = (uint32_t)(mbar_smem_addr);                                             \
    uint32_t _parity = (uint32_t)(phase_parity);                                             \
    uint32_t _done;                                                                          \
    asm volatile("{\n\t.reg .pred p;\n\t"                                                    \
        "mbarrier.try_wait.parity.acquire.cta.shared::cta.b64 p, [%1], %2;\n\t"              \
        "selp.b32 %0, 1, 0, p;\n\t}"                                                         \
        : "=r"(_done) : "r"(_mbar), "r"(_parity) : "memory");                                \
    if (!_done) {                                                                            \
        asm volatile("{\n\t.reg .pred P1;\n\t"                                               \
            "WAIT_LOOP_%=:\n\t"                                                              \
            "mbarrier.try_wait.parity.acquire.cta.shared::cta.b64 P1, [%0], %1, 0x989680;\n\t" \
            "@P1 bra.uni WAIT_DONE_%=;\n\t"                                                  \
            "bra.uni WAIT_LOOP_%=;\n\t"                                                      \
            "WAIT_DONE_%=:\n\t}"                                                             \
            :: "r"(_mbar), "r"(_parity) : "memory");                                         \
    }                                                                                        \
} while (0)

#define TCGEN05_ALLOC(smem_addr, nCols) \
    asm volatile("tcgen05.alloc.cta_group::1.sync.aligned.shared::cta.b32 [%0], %1;" \
                 :: "r"((uint32_t)(smem_addr)), "r"((uint32_t)(nCols)) : "memory")
#define TCGEN05_DEALLOC(tmem_addr, nCols) \
    asm volatile("tcgen05.dealloc.cta_group::1.sync.aligned.b32 %0, %1;" \
                 :: "r"(tmem_addr), "r"((uint32_t)(nCols)))
#define TCGEN05_RELINQUISH() \
    asm volatile("tcgen05.relinquish_alloc_permit.cta_group::1.sync.aligned;")
#define TCGEN05_COMMIT(mbar) \
    asm volatile("tcgen05.commit.cta_group::1.mbarrier::arrive::one.shared::cluster.b64 [%0];" \
                 :: "r"((uint32_t)(mbar)) : "memory")
#define TCGEN05_FENCE_AFTER()  asm volatile("tcgen05.fence::after_thread_sync;" ::: "memory")
#define TCGEN05_FENCE_BEFORE() asm volatile("tcgen05.fence::before_thread_sync;" ::: "memory")
#define TCGEN05_WAIT_LD()      asm volatile("tcgen05.wait::ld.sync.aligned;" ::: "memory")
#define FENCE_PROXY_ASYNC()    asm volatile("fence.proxy.async.shared::cta;" ::: "memory")

#define TCGEN05_LD_32X32B_X32(r, tmem_addr) \
    asm volatile( \
        "tcgen05.ld.sync.aligned.32x32b.x32.b32 " \
        "{%0, %1, %2, %3, %4, %5, %6, %7, " \
        " %8, %9, %10, %11, %12, %13, %14, %15, " \
        " %16, %17, %18, %19, %20, %21, %22, %23, " \
        " %24, %25, %26, %27, %28, %29, %30, %31}, [%32];" \
        : "=r"((r)[0]),  "=r"((r)[1]),  "=r"((r)[2]),  "=r"((r)[3]), \
          "=r"((r)[4]),  "=r"((r)[5]),  "=r"((r)[6]),  "=r"((r)[7]), \
          "=r"((r)[8]),  "=r"((r)[9]),  "=r"((r)[10]), "=r"((r)[11]), \
          "=r"((r)[12]), "=r"((r)[13]), "=r"((r)[14]), "=r"((r)[15]), \
          "=r"((r)[16]), "=r"((r)[17]), "=r"((r)[18]), "=r"((r)[19]), \
          "=r"((r)[20]), "=r"((r)[21]), "=r"((r)[22]), "=r"((r)[23]), \
          "=r"((r)[24]), "=r"((r)[25]), "=r"((r)[26]), "=r"((r)[27]), \
          "=r"((r)[28]), "=r"((r)[29]), "=r"((r)[30]), "=r"((r)[31]) \
        : "r"(tmem_addr))

__device__ __forceinline__ void mma_f16_ss(uint32_t d, uint64_t a, uint64_t b,
                                           uint32_t idesc, uint32_t en) {
#if defined(__CUDA_ARCH_FEAT_SM103_ALL)
    asm volatile(
        "{\n\t"
        ".reg .pred p;\n\t"
        "setp.ne.u32 p, %5, 0;\n\t"
        "tcgen05.mma.cta_group::1.kind::f16 [%0], %1, %2, %3, {%4, %4, %4, %4}, p;\n\t"
        "}"
        :: "r"(d), "l"(a), "l"(b), "r"(idesc), "r"(0u), "r"(en)
        : "memory");
#endif
}

// ---------------------------------------------------------------- fallback (mma.sync) helpers
#define LDMATRIX_X4(r0, r1, r2, r3, addr) \
    asm volatile("ldmatrix.sync.aligned.m8n8.x4.shared.b16 {%0,%1,%2,%3}, [%4];" \
                 : "=r"(r0), "=r"(r1), "=r"(r2), "=r"(r3) : "r"(addr))

#define MMA16816(d, a0, a1, a2, a3, b0, b1) \
    asm volatile("mma.sync.aligned.m16n8k16.row.col.f32.f16.f16.f32 " \
                 "{%0,%1,%2,%3}, {%4,%5,%6,%7}, {%8,%9}, {%0,%1,%2,%3};" \
                 : "+f"((d)[0]), "+f"((d)[1]), "+f"((d)[2]), "+f"((d)[3]) \
                 : "r"(a0), "r"(a1), "r"(a2), "r"(a3), "r"(b0), "r"(b1))

// ---------------------------------------------------------------- kernel 1: x -> fp16
__global__ void k_convert(const float* __restrict__ x) {
    size_t i = (size_t)blockIdx.x * blockDim.x + threadIdx.x;   // one float4
    const float4 v = reinterpret_cast<const float4*>(x)[i];
    __half2* o = reinterpret_cast<__half2*>(g_xh) + 2 * i;
    o[0] = __floats2half2_rn(v.x, v.y);
    o[1] = __floats2half2_rn(v.z, v.w);
}

// ---------------------------------------------------------------- kernel 2: dequant W -> wT[N,K] fp16
__global__ void k_dequant(const int* __restrict__ qweight, const int* __restrict__ qzeros,
                          const float* __restrict__ scales) {
    const int NB = OUT_F / 256;                       // 43
    int n  = (blockIdx.x % NB) * 256 + threadIdx.x;   // output column
    int kb = blockIdx.x / NB;                         // block of 4 qweight rows (32 k)
    int g  = kb >> 2;                                 // group (GSIZE=128 => 16 q-rows/group)
    uint32_t qz = (uint32_t)qzeros[g * (OUT_F / 8) + (n >> 3)];
    float z1 = (float)(((qz >> ((n & 7) * 4)) & 0xF) + 1);
    float sc = scales[g * OUT_F + n];
    float base = -sc * z1;

    alignas(16) __half h[32];
#pragma unroll
    for (int i = 0; i < 4; i++) {
        uint32_t q = (uint32_t)qweight[(size_t)(kb * 4 + i) * OUT_F + n];
#pragma unroll
        for (int j = 0; j < 8; j++)
            h[i * 8 + j] = __float2half(sc * (float)((q >> (4 * j)) & 0xF) + base);
    }
    uint4* dst = reinterpret_cast<uint4*>(&g_wT[(size_t)n * IN_F + kb * 32]);
    const uint4* src = reinterpret_cast<const uint4*>(h);
    dst[0] = src[0]; dst[1] = src[1]; dst[2] = src[2]; dst[3] = src[3];
}

// ---------------------------------------------------------------- kernel 3: GEMM
// CTA tile: M=128, N=256, K-chunk=64 fp16 (128B rows, SW128).
static constexpr int BM = 128, BN = 256, BK = 64;
static constexpr int STAGES = 4;
static constexpr int A_BYTES = BM * 128;              // 16384
static constexpr int B_BYTES = BN * 128;              // 32768
static constexpr int STAGE_BYTES = A_BYTES + B_BYTES; // 49152
static constexpr int SMEM_TILES = 1024;
static constexpr int SMEM_TOTAL = SMEM_TILES + STAGES * STAGE_BYTES; // 197632
static constexpr int K_ITERS = IN_F / BK;             // 64
// idesc: f32 accum(1<<4), fp16 A/B (0), N/8 << 17, M/16 << 24
static constexpr uint32_t IDESC = (1u << 4) | ((BN / 8) << 17) | ((BM / 16) << 24);

__global__ __launch_bounds__(256, 1) void k_gemm(const float* __restrict__ bias,
                                                 float* __restrict__ out) {
#if defined(__CUDA_ARCH_FEAT_SM103_ALL)
    // =================== tcgen05 path (sm_103a cubin) ===================
    extern __shared__ char smem[];
    const uint32_t smem_base = smem_u32(smem);
    const int tid = threadIdx.x;
    const int wid = tid >> 5;
    const int lid = tid & 31;
    const int NB = OUT_F / BN;                        // 43
    const int n0 = (blockIdx.x % NB) * BN;
    const int m0 = (blockIdx.x / NB) * BM;

    if (wid == 0) TCGEN05_ALLOC(smem_base + 0, 256);
    if (tid == 0) {
#pragma unroll
        for (int s = 0; s < STAGES; s++) MBARRIER_INIT(smem_base + 16 + 8 * s, 1);
    }
    __syncthreads();
    uint32_t tmem;
    asm volatile("ld.shared.b32 %0, [%1];" : "=r"(tmem) : "r"(smem_base));

    const __half* ga_base = g_xh + (size_t)m0 * IN_F;
    const __half* gb_base = g_wT + (size_t)n0 * IN_F;

    auto load_stage = [&](int j) {
        const int s = j & (STAGES - 1);
        const uint32_t sa = smem_base + SMEM_TILES + s * STAGE_BYTES;
        const uint32_t sb = sa + A_BYTES;
        const __half* ga = ga_base + j * BK;
        const __half* gb = gb_base + j * BK;
#pragma unroll
        for (int c = 0; c < 4; c++) {                 // A: 1024 x 16B chunks
            int idx = tid + c * 256;
            int row = idx >> 3, kc = idx & 7;
            uint32_t off = (uint32_t)(row * 128 + kc * 16);
            CP_ASYNC16(sa + SWZ128(off), ga + (size_t)row * IN_F + kc * 8);
        }
#pragma unroll
        for (int c = 0; c < 8; c++) {                 // B: 2048 x 16B chunks
            int idx = tid + c * 256;
            int row = idx >> 3, kc = idx & 7;
            uint32_t off = (uint32_t)(row * 128 + kc * 16);
            CP_ASYNC16(sb + SWZ128(off), gb + (size_t)row * IN_F + kc * 8);
        }
    };

    load_stage(0); CP_COMMIT();
    load_stage(1); CP_COMMIT();
    load_stage(2); CP_COMMIT();

    for (int it = 0; it < K_ITERS; ++it) {
        const int s = it & (STAGES - 1);
        CP_WAIT2();
        __syncthreads();                               // stage s fully in SMEM, CTA-visible
        if (tid == 0) {
            FENCE_PROXY_ASYNC();
            const uint32_t base = smem_base + SMEM_TILES + s * STAGE_BYTES;
            uint64_t ad = MAKE_SMEM_DESC(base);
            uint64_t bd = MAKE_SMEM_DESC(base + A_BYTES);
#pragma unroll
            for (int kk = 0; kk < 4; kk++)             // 4 x K=16 MMAs per K-chunk
                mma_f16_ss(tmem, ad + kk * 2, bd + kk * 2, IDESC, (uint32_t)(it | kk));
            TCGEN05_COMMIT(smem_base + 16 + 8 * s);
        }
        const int j = it + (STAGES - 1);
        if (j < K_ITERS) {
            if (j >= STAGES) {
                MBARRIER_WAIT_PARITY(smem_base + 16 + 8 * (j & (STAGES - 1)),
                                     ((j >> 2) + 1) & 1);
            }
            load_stage(j);
        }
        CP_COMMIT();
    }

    MBARRIER_WAIT_PARITY(smem_base + 16 + 8 * 3, 1);
    TCGEN05_FENCE_AFTER();

    const int colbase = (wid >> 2) * 128;
    const int m = m0 + (wid & 3) * 32 + lid;
    float* orow = out + (size_t)m * OUT_F + n0 + colbase;
    const float* brow = bias + n0 + colbase;
#pragma unroll
    for (int ch = 0; ch < 4; ch++) {
        uint32_t d[32];
        TCGEN05_LD_32X32B_X32(d, tmem + colbase + ch * 32);
        TCGEN05_WAIT_LD();
#pragma unroll
        for (int c = 0; c < 32; c += 4) {
            float4 b4 = *reinterpret_cast<const float4*>(brow + ch * 32 + c);
            float4 v;
            v.x = __uint_as_float(d[c + 0]) + b4.x;
            v.y = __uint_as_float(d[c + 1]) + b4.y;
            v.z = __uint_as_float(d[c + 2]) + b4.z;
            v.w = __uint_as_float(d[c + 3]) + b4.w;
            *reinterpret_cast<float4*>(orow + ch * 32 + c) = v;
        }
    }
    TCGEN05_FENCE_BEFORE();
    __syncthreads();
    if (wid == 0) {
        TCGEN05_RELINQUISH();
        TCGEN05_DEALLOC(tmem, 256);
    }
#else
    // =================== mma.sync fallback (generic compute_103 pass) ===================
    extern __shared__ char smem[];
    const uint32_t smem_base = smem_u32(smem);
    const int tid = threadIdx.x;
    const int wid = tid >> 5;
    const int lane = tid & 31;
    const int NB = OUT_F / BN;
    const int n0 = (blockIdx.x % NB) * BN;
    const int m0 = (blockIdx.x / NB) * BM;
    const int wm = (wid >> 2) * 64;                    // warp m offset within CTA tile
    const int wn = (wid & 3) * 64;                     // warp n offset

    const __half* ga_base = g_xh + (size_t)m0 * IN_F;
    const __half* gb_base = g_wT + (size_t)n0 * IN_F;

    auto load_stage2 = [&](int j) {
        const int s = j & 1;
        const uint32_t sa = smem_base + s * STAGE_BYTES;
        const uint32_t sb = sa + A_BYTES;
        const __half* ga = ga_base + j * BK;
        const __half* gb = gb_base + j * BK;
#pragma unroll
        for (int c = 0; c < 4; c++) {
            int idx = tid + c * 256;
            int row = idx >> 3, kc = idx & 7;
            uint32_t off = (uint32_t)(row * 128 + kc * 16);
            CP_ASYNC16(sa + SWZ128(off), ga + (size_t)row * IN_F + kc * 8);
        }
#pragma unroll
        for (int c = 0; c < 8; c++) {
            int idx = tid + c * 256;
            int row = idx >> 3, kc = idx & 7;
            uint32_t off = (uint32_t)(row * 128 + kc * 16);
            CP_ASYNC16(sb + SWZ128(off), gb + (size_t)row * IN_F + kc * 8);
        }
    };

    float acc[4][8][4];                                // 4 m-tiles x 8 n-tiles x 4 regs
#pragma unroll
    for (int i = 0; i < 4; i++)
#pragma unroll
        for (int j = 0; j < 8; j++)
#pragma unroll
            for (int r = 0; r < 4; r++) acc[i][j][r] = 0.f;

    load_stage2(0); CP_COMMIT();

    const int lr = lane & 7, lq = lane >> 3;           // ldmatrix lane mapping
    for (int it = 0; it < K_ITERS; ++it) {
        if (it + 1 < K_ITERS) { load_stage2(it + 1); CP_COMMIT(); CP_WAIT1(); }
        else                  { CP_WAIT0(); }
        __syncthreads();
        const uint32_t sa = smem_base + (it & 1) * STAGE_BYTES;
        const uint32_t sb = sa + A_BYTES;
#pragma unroll
        for (int k16 = 0; k16 < 4; k16++) {
            const uint32_t koff = k16 * 32 + (lq >> 1) * 16;
            uint32_t a[4][4], b[4][4];
#pragma unroll
            for (int mt = 0; mt < 4; mt++) {
                uint32_t row = (uint32_t)(wm + mt * 16 + lr + (lq & 1) * 8);
                uint32_t addr = sa + SWZ128(row * 128 + koff);
                LDMATRIX_X4(a[mt][0], a[mt][1], a[mt][2], a[mt][3], addr);
            }
#pragma unroll
            for (int nt = 0; nt < 4; nt++) {
                uint32_t row = (uint32_t)(wn + nt * 16 + lr + (lq & 1) * 8);
                uint32_t addr = sb + SWZ128(row * 128 + koff);
                LDMATRIX_X4(b[nt][0], b[nt][1], b[nt][2], b[nt][3], addr);
            }
#pragma unroll
            for (int mt = 0; mt < 4; mt++)
#pragma unroll
                for (int nt = 0; nt < 4; nt++) {
                    MMA16816(acc[mt][nt * 2 + 0], a[mt][0], a[mt][1], a[mt][2], a[mt][3],
                             b[nt][0], b[nt][2]);
                    MMA16816(acc[mt][nt * 2 + 1], a[mt][0], a[mt][1], a[mt][2], a[mt][3],
                             b[nt][1], b[nt][3]);
                }
        }
        __syncthreads();
    }

    // Epilogue: c-fragment mapping of m16n8: rows lane>>2 (+8), cols (lane&3)*2, +1
#pragma unroll
    for (int mt = 0; mt < 4; mt++) {
#pragma unroll
        for (int nt = 0; nt < 8; nt++) {
            int m = m0 + wm + mt * 16 + (lane >> 2);
            int n = n0 + wn + nt * 8 + (lane & 3) * 2;
            float b0 = bias[n], b1 = bias[n + 1];
            float2 v0 = make_float2(acc[mt][nt][0] + b0, acc[mt][nt][1] + b1);
            float2 v1 = make_float2(acc[mt][nt][2] + b0, acc[mt][nt][3] + b1);
            *reinterpret_cast<float2*>(out + (size_t)m * OUT_F + n) = v0;
            *reinterpret_cast<float2*>(out + (size_t)(m + 8) * OUT_F + n) = v1;
        }
    }
#endif
}

// ---------------------------------------------------------------- launch
extern "C" void kernel_launch(void* const* d_in, const int* in_sizes, int n_in,
                              void* d_out, int out_size) {
    const float* x       = (const float*)d_in[0];
    const int*   qweight = (const int*)  d_in[1];
    const int*   qzeros  = (const int*)  d_in[2];
    const float* scales  = (const float*)d_in[3];
    // d_in[4] = g_idx (implicitly i/128, hardcoded)
    const float* bias    = (const float*)d_in[5];
    float* out = (float*)d_out;

    k_convert<<<(TOKENS * IN_F) / (256 * 4), 256>>>(x);
    k_dequant<<<(OUT_F / 256) * (IN_F / 32), 256>>>(qweight, qzeros, scales);

    cudaFuncSetAttribute(k_gemm, cudaFuncAttributeMaxDynamicSharedMemorySize, SMEM_TOTAL);
    k_gemm<<<(OUT_F / BN) * (TOKENS / BM), 256, SMEM_TOTAL>>>(bias, out);
}